// round 1
// baseline (speedup 1.0000x reference)
#include <cuda_runtime.h>
#include <math.h>

#define Bn 2
#define Tn 192
#define NBn 62
#define HID 256
#define DIN 512
#define NHEADS 8
#define HEADP 64
#define DSTATE 64
#define CONVDIM 640
#define PROJ 1160
#define NTOK (Bn*Tn*NBn)          /* 23808 */
#define CBMAX (124*192*192)       /* t-axis CB scratch is the max */

/* ------------ device-global scratch (no cudaMalloc allowed) ------------ */
__device__ float g_xn [NTOK*HID];        /* rmsnorm'd input, [tok,256]   */
__device__ float g_Z  [NTOK*PROJ];       /* in-proj output,  [tok,1160]  */
__device__ float g_xBC[NTOK*CONVDIM];    /* conv+silu,       [tok,640]   */
__device__ float g_dt [NTOK*NHEADS];     /* softplus dt,     [tok,8]     */
__device__ float g_cum[NTOK*NHEADS];     /* cumsum(dt*A), [(seq*8+h),L]  */
__device__ float g_CB [CBMAX];           /* C.B^T scores, [seq,L,L]      */
__device__ float g_y  [NTOK*DIN];        /* ssd out / gated, [tok,512]   */

/* token (seq,t) -> offset into the (B,T,NB,H) activation tensor */
__device__ __forceinline__ int xoff(int axis, int seq, int t)
{
    if (axis == 0) {                       /* t-axis: seq=(b,nb), pos=t  */
        int b = seq / NBn, nb = seq - b*NBn;
        return ((b*Tn + t)*NBn + nb)*HID;
    }
    return (seq*NBn + t)*HID;              /* b-axis: contiguous          */
}

/* ------------------ 1. strided gather + RMSNorm(256) ------------------ */
__global__ void k_rmsnorm(const float* __restrict__ x, const float* __restrict__ w,
                          int axis, int L)
{
    int tok = blockIdx.x*8 + (threadIdx.x >> 5);
    if (tok >= NTOK) return;
    int lane = threadIdx.x & 31;
    int seq = tok / L, t = tok - seq*L;
    const float* xp = x + xoff(axis, seq, t);
    float v[8]; float ss = 0.f;
#pragma unroll
    for (int i = 0; i < 8; i++) { v[i] = xp[lane + 32*i]; ss += v[i]*v[i]; }
#pragma unroll
    for (int o = 16; o; o >>= 1) ss += __shfl_xor_sync(0xffffffffu, ss, o);
    float r = rsqrtf(ss*(1.f/HID) + 1e-6f);
    float* op = g_xn + tok*HID;
#pragma unroll
    for (int i = 0; i < 8; i++) op[lane + 32*i] = v[i]*r*w[lane + 32*i];
}

/* --------- 2/8. SGEMM 64x64x16 tiles, 4x4 micro-tile per thread ------- */
/* asel: 0 -> A=g_xn (K=256), 1 -> A=g_y (K=512)                          */
/* mode: 0 -> write g_Z[row*PROJ+col]; 1 -> residual scatter-add into x   */
__global__ void k_sgemm(int asel, const float* __restrict__ Bw,
                        int N, int K, int mode, float* xout, int axis, int L)
{
    __shared__ float As[16][68];   /* [k][m], padded for f4 alignment */
    __shared__ float Bs[16][64];   /* [k][n] */
    int m0 = blockIdx.y*64, n0 = blockIdx.x*64;
    int tid = threadIdx.x;
    int tx = tid & 15, ty = tid >> 4;
    const float* A = asel ? g_y : g_xn;
    float acc[4][4] = {};
    int ca = tid & 15, ra = tid >> 4;
    int cb = tid & 63, rb = tid >> 6;

    for (int kt = 0; kt < K; kt += 16) {
#pragma unroll
        for (int i = 0; i < 4; i++)
            As[ca][ra + 16*i] = A[(m0 + ra + 16*i)*K + kt + ca];
#pragma unroll
        for (int i = 0; i < 4; i++) {
            int nn = n0 + cb;
            Bs[rb + 4*i][cb] = (nn < N) ? Bw[(kt + rb + 4*i)*N + nn] : 0.f;
        }
        __syncthreads();
#pragma unroll
        for (int k = 0; k < 16; k++) {
            float4 a = *(const float4*)&As[k][ty*4];
            float4 b = *(const float4*)&Bs[k][tx*4];
            acc[0][0]+=a.x*b.x; acc[0][1]+=a.x*b.y; acc[0][2]+=a.x*b.z; acc[0][3]+=a.x*b.w;
            acc[1][0]+=a.y*b.x; acc[1][1]+=a.y*b.y; acc[1][2]+=a.y*b.z; acc[1][3]+=a.y*b.w;
            acc[2][0]+=a.z*b.x; acc[2][1]+=a.z*b.y; acc[2][2]+=a.z*b.z; acc[2][3]+=a.z*b.w;
            acc[3][0]+=a.w*b.x; acc[3][1]+=a.w*b.y; acc[3][2]+=a.w*b.z; acc[3][3]+=a.w*b.w;
        }
        __syncthreads();
    }

    if (mode == 0) {
#pragma unroll
        for (int i = 0; i < 4; i++) {
            int row = m0 + ty*4 + i;
#pragma unroll
            for (int j = 0; j < 4; j++) {
                int col = n0 + tx*4 + j;
                if (col < N) g_Z[row*PROJ + col] = acc[i][j];
            }
        }
    } else {
#pragma unroll
        for (int i = 0; i < 4; i++) {
            int row = m0 + ty*4 + i;
            int seq = row / L, t = row - seq*L;
            float* op = xout + xoff(axis, seq, t);
#pragma unroll
            for (int j = 0; j < 4; j++) op[n0 + tx*4 + j] += acc[i][j];
        }
    }
}

/* ------- 3. causal conv(K=4)+SiLU over 640 ch, plus softplus(dt) ------- */
__global__ void k_convdt(const float* __restrict__ Wc, const float* __restrict__ bc,
                         const float* __restrict__ dtb, int L)
{
    int idx = blockIdx.x*256 + threadIdx.x;
    if (idx >= NTOK*(CONVDIM + NHEADS)) return;
    int tok = idx / (CONVDIM + NHEADS);
    int c   = idx - tok*(CONVDIM + NHEADS);
    int seq = tok / L, t = tok - seq*L;
    if (c < CONVDIM) {
        float acc = bc[c];
#pragma unroll
        for (int k = 0; k < 4; k++) {
            int tt = t - 3 + k;
            if (tt >= 0) acc += Wc[c*4 + k] * g_Z[(seq*L + tt)*PROJ + DIN + c];
        }
        g_xBC[tok*CONVDIM + c] = acc / (1.f + __expf(-acc));
    } else {
        int h = c - CONVDIM;
        float v = g_Z[tok*PROJ + DIN + CONVDIM + h] + dtb[h];
        g_dt[tok*NHEADS + h] = (v > 20.f) ? v : log1pf(__expf(v));
    }
}

/* ----------------- 4. per-(seq,head) cumsum of dt*A -------------------- */
__global__ void k_scan(const float* __restrict__ Alog, int L, int nseq)
{
    int i = blockIdx.x*64 + threadIdx.x;
    if (i >= nseq*NHEADS) return;
    int seq = i >> 3, h = i & 7;
    float A = -expf(Alog[h]);
    float c = 0.f;
    float* cp = g_cum + i*L;
    const float* dp = g_dt + seq*L*NHEADS + h;
    for (int t = 0; t < L; t++) { c += dp[t*NHEADS]*A; cp[t] = c; }
}

/* ------------------- 5. CB[l,s] = sum_n C[l,n]*B[s,n] ------------------ */
__global__ void k_cb(int L)
{
    __shared__ float Ct[64][65], Bt[64][65];   /* [n][l], [n][s] */
    int seq = blockIdx.x;
    int l0 = blockIdx.y*64, s0 = blockIdx.z*64;
    int tid = threadIdx.x;
    int n = tid & 63, r = tid >> 6;
#pragma unroll 4
    for (int i = 0; i < 16; i++) {
        int row = r + 4*i;
        int gl = l0 + row, gs = s0 + row;
        Ct[n][row] = (gl < L) ? g_xBC[(seq*L + gl)*CONVDIM + DIN + DSTATE + n] : 0.f;
        Bt[n][row] = (gs < L) ? g_xBC[(seq*L + gs)*CONVDIM + DIN + n]          : 0.f;
    }
    __syncthreads();
    int tx = tid & 15, ty = tid >> 4;
    float acc[4][4] = {};
#pragma unroll 8
    for (int k = 0; k < 64; k++) {
        float a0=Ct[k][ty*4], a1=Ct[k][ty*4+1], a2=Ct[k][ty*4+2], a3=Ct[k][ty*4+3];
        float b0=Bt[k][tx*4], b1=Bt[k][tx*4+1], b2=Bt[k][tx*4+2], b3=Bt[k][tx*4+3];
        acc[0][0]+=a0*b0; acc[0][1]+=a0*b1; acc[0][2]+=a0*b2; acc[0][3]+=a0*b3;
        acc[1][0]+=a1*b0; acc[1][1]+=a1*b1; acc[1][2]+=a1*b2; acc[1][3]+=a1*b3;
        acc[2][0]+=a2*b0; acc[2][1]+=a2*b1; acc[2][2]+=a2*b2; acc[2][3]+=a2*b3;
        acc[3][0]+=a3*b0; acc[3][1]+=a3*b1; acc[3][2]+=a3*b2; acc[3][3]+=a3*b3;
    }
#pragma unroll
    for (int i = 0; i < 4; i++) {
        int gl = l0 + ty*4 + i;
#pragma unroll
        for (int j = 0; j < 4; j++) {
            int gs = s0 + tx*4 + j;
            if (gl < L && gs < L) g_CB[(seq*L + gl)*L + gs] = acc[i][j];
        }
    }
}

/* --- 6. SSD: y[l,h,:] = sum_s CB[l,s]*w(l,s,h)*dt[s,h]*xh[s,h,:] -------
 * combined fwd (s<l: exp(cum[l]-cum[s])) + bwd (s>l: exp(cum[s-1]-cum[l-1]))
 * diagonal counted twice (both triangular passes include it).            */
__global__ void k_ssd(const float* __restrict__ Alog, int L)
{
    __shared__ float cum[192], dts[192];
    __shared__ float Wt[64][65];   /* [s][l] */
    __shared__ float Xs[64][68];   /* [s][p] */
    int seq = blockIdx.x, h = blockIdx.y, l0 = blockIdx.z*64;
    int tid = threadIdx.x;
    float A = -expf(Alog[h]);
    for (int t = tid; t < L; t += 256) {
        cum[t] = g_cum[(seq*NHEADS + h)*L + t];
        dts[t] = g_dt[(seq*L + t)*NHEADS + h];
    }
    __syncthreads();

    int tx = tid & 15, ty = tid >> 4;
    int fc = tid & 63, fr = tid >> 6;
    float acc[4][4] = {};

    for (int s0 = 0; s0 < L; s0 += 64) {
#pragma unroll 4
        for (int i = 0; i < 16; i++) {           /* load xh tile */
            int s = fr + 4*i;
            int gs = s0 + s;
            Xs[s][fc] = (gs < L) ? g_xBC[(seq*L + gs)*CONVDIM + h*HEADP + fc] : 0.f;
        }
#pragma unroll 4
        for (int i = 0; i < 16; i++) {           /* build weight tile */
            int lW = fr + 4*i, sW = fc;
            int gl = l0 + lW, gs = s0 + sW;
            float w = 0.f;
            if (gl < L && gs < L) {
                float cb = g_CB[(seq*L + gl)*L + gs];
                float e;
                if (gs < gl)       e = __expf(cum[gl] - cum[gs]);
                else if (gs == gl) e = 2.f;
                else               e = __expf((cum[gs] - dts[gs]*A) - (cum[gl] - dts[gl]*A));
                w = cb * e * dts[gs];
            }
            Wt[sW][lW] = w;
        }
        __syncthreads();
#pragma unroll 8
        for (int k = 0; k < 64; k++) {
            float a0=Wt[k][ty*4], a1=Wt[k][ty*4+1], a2=Wt[k][ty*4+2], a3=Wt[k][ty*4+3];
            float4 b = *(const float4*)&Xs[k][tx*4];
            acc[0][0]+=a0*b.x; acc[0][1]+=a0*b.y; acc[0][2]+=a0*b.z; acc[0][3]+=a0*b.w;
            acc[1][0]+=a1*b.x; acc[1][1]+=a1*b.y; acc[1][2]+=a1*b.z; acc[1][3]+=a1*b.w;
            acc[2][0]+=a2*b.x; acc[2][1]+=a2*b.y; acc[2][2]+=a2*b.z; acc[2][3]+=a2*b.w;
            acc[3][0]+=a3*b.x; acc[3][1]+=a3*b.y; acc[3][2]+=a3*b.z; acc[3][3]+=a3*b.w;
        }
        __syncthreads();
    }
#pragma unroll
    for (int i = 0; i < 4; i++) {
        int gl = l0 + ty*4 + i;
        if (gl < L) {
            float* yp = g_y + (seq*L + gl)*DIN + h*HEADP;
#pragma unroll
            for (int j = 0; j < 4; j++) yp[tx*4 + j] = acc[i][j];
        }
    }
}

/* ---------- 7. (y + D*xh) * silu(z), then RMSNorm(512) * gn_w ---------- */
__global__ void k_gate(const float* __restrict__ Dv, const float* __restrict__ gnw)
{
    __shared__ float red[8];
    int tok = blockIdx.x, tid = threadIdx.x;
    float v[2]; float ss = 0.f;
#pragma unroll
    for (int i = 0; i < 2; i++) {
        int d = tid + 256*i;
        float y = g_y[tok*DIN + d] + Dv[d >> 6]*g_xBC[tok*CONVDIM + d];
        float z = g_Z[tok*PROJ + d];
        y *= z / (1.f + __expf(-z));
        v[i] = y; ss += y*y;
    }
#pragma unroll
    for (int o = 16; o; o >>= 1) ss += __shfl_xor_sync(0xffffffffu, ss, o);
    if ((tid & 31) == 0) red[tid >> 5] = ss;
    __syncthreads();
    if (tid < 32) {
        float s = (tid < 8) ? red[tid] : 0.f;
#pragma unroll
        for (int o = 4; o; o >>= 1) s += __shfl_xor_sync(0xffffffffu, s, o);
        if (tid == 0) red[0] = s;
    }
    __syncthreads();
    float r = rsqrtf(red[0]*(1.f/DIN) + 1e-6f);
#pragma unroll
    for (int i = 0; i < 2; i++) {
        int d = tid + 256*i;
        g_y[tok*DIN + d] = v[i]*r*gnw[d];
    }
}

/* ----------------------------- host side ------------------------------ */
static void run_call(float* out, const float* const* P, int li, int axis)
{
    const float* nw   = P[0] + li*HID;
    const float* Win  = P[1] + li*HID*PROJ;
    const float* Wc   = P[2] + li*CONVDIM*4;
    const float* bc   = P[3] + li*CONVDIM;
    const float* dtb  = P[4] + li*NHEADS;
    const float* Alog = P[5] + li*NHEADS;
    const float* Dv   = P[6] + li*NHEADS;
    const float* gnw  = P[7] + li*DIN;
    const float* Wout = P[8] + li*DIN*HID;
    int L = (axis == 0) ? Tn : NBn;
    int nseq = NTOK / L;
    int lt = (L + 63)/64;

    k_rmsnorm<<<NTOK/8, 256>>>(out, nw, axis, L);
    k_sgemm<<<dim3((PROJ + 63)/64, NTOK/64), 256>>>(0, Win, PROJ, HID, 0, nullptr, axis, L);
    k_convdt<<<(NTOK*(CONVDIM + NHEADS) + 255)/256, 256>>>(Wc, bc, dtb, L);
    k_scan<<<(nseq*NHEADS + 63)/64, 64>>>(Alog, L, nseq);
    k_cb<<<dim3(nseq, lt, lt), 256>>>(L);
    k_ssd<<<dim3(nseq, NHEADS, lt), 256>>>(Alog, L);
    k_gate<<<NTOK, 256>>>(Dv, gnw);
    k_sgemm<<<dim3(HID/64, NTOK/64), 256>>>(1, Wout, HID, DIN, 1, out, axis, L);
}

extern "C" void kernel_launch(void* const* d_in, const int* in_sizes, int n_in,
                              void* d_out, int out_size)
{
    float* out = (float*)d_out;
    cudaMemcpyAsync(out, d_in[0], (size_t)out_size*sizeof(float),
                    cudaMemcpyDeviceToDevice);
    const float* tp[9]; const float* bp[9];
    for (int i = 0; i < 9; i++) {
        tp[i] = (const float*)d_in[1 + i];
        bp[i] = (const float*)d_in[10 + i];
    }
    for (int li = 0; li < 2; li++) {
        run_call(out, tp, li, 0);   /* time axis   */
        run_call(out, bp, li, 1);   /* block axis  */
    }
}

// round 2
// speedup vs baseline: 1.0517x; 1.0517x over previous
#include <cuda_runtime.h>
#include <math.h>

#define Bn 2
#define Tn 192
#define NBn 62
#define HID 256
#define DIN 512
#define NHEADS 8
#define HEADP 64
#define DSTATE 64
#define CONVDIM 640
#define PROJ 1160
#define NTOK (Bn*Tn*NBn)          /* 23808 */
#define CBMAX (124*192*192)       /* t-axis CB scratch is the max */

/* ------------ device-global scratch (no cudaMalloc allowed) ------------ */
__device__ float g_xn [NTOK*HID];        /* rmsnorm'd input, [tok,256]   */
__device__ float g_Z  [NTOK*PROJ];       /* in-proj output,  [tok,1160]  */
__device__ float g_xBC[NTOK*CONVDIM];    /* conv+silu,       [tok,640]   */
__device__ float g_dt [NTOK*NHEADS];     /* softplus dt,     [tok,8]     */
__device__ float g_CB [CBMAX];           /* B.C^T scores, [seq,s,l]      */
__device__ float g_y  [NTOK*DIN];        /* ssd out / gated, [tok,512]   */

/* token (seq,t) -> offset into the (B,T,NB,H) activation tensor */
__device__ __forceinline__ int xoff(int axis, int seq, int t)
{
    if (axis == 0) {                       /* t-axis: seq=(b,nb), pos=t  */
        int b = seq / NBn, nb = seq - b*NBn;
        return ((b*Tn + t)*NBn + nb)*HID;
    }
    return (seq*NBn + t)*HID;              /* b-axis: contiguous          */
}

/* ------------------ 1. strided gather + RMSNorm(256) ------------------ */
__global__ void k_rmsnorm(const float* __restrict__ x, const float* __restrict__ w,
                          int axis, int L)
{
    int tok = blockIdx.x*8 + (threadIdx.x >> 5);
    if (tok >= NTOK) return;
    int lane = threadIdx.x & 31;
    int seq = tok / L, t = tok - seq*L;
    const float* xp = x + xoff(axis, seq, t);
    float v[8]; float ss = 0.f;
#pragma unroll
    for (int i = 0; i < 8; i++) { v[i] = xp[lane + 32*i]; ss += v[i]*v[i]; }
#pragma unroll
    for (int o = 16; o; o >>= 1) ss += __shfl_xor_sync(0xffffffffu, ss, o);
    float r = rsqrtf(ss*(1.f/HID) + 1e-6f);
    float* op = g_xn + tok*HID;
#pragma unroll
    for (int i = 0; i < 8; i++) op[lane + 32*i] = v[i]*r*w[lane + 32*i];
}

/* --------- 2/8. SGEMM 64x64x16 tiles, 4x4 micro-tile, prefetched ------ */
/* asel: 0 -> A=g_xn (K=256), 1 -> A=g_y (K=512)                          */
/* mode: 0 -> write g_Z[row*PROJ+col]; 1 -> residual scatter-add into x   */
__global__ void k_sgemm(int asel, const float* __restrict__ Bw,
                        int N, int K, int mode, float* xout, int axis, int L)
{
    __shared__ __align__(16) float As[16][68];   /* [k][m] */
    __shared__ __align__(16) float Bs[16][64];   /* [k][n] */
    int m0 = blockIdx.y*64, n0 = blockIdx.x*64;
    int tid = threadIdx.x;
    int tx = tid & 15, ty = tid >> 4;
    const float* A = asel ? g_y : g_xn;
    float acc[4][4] = {};
    int ca = tid & 15, ra = tid >> 4;
    int cb = tid & 63, rb = tid >> 6;
    int bok = (n0 + cb) < N;

    float pa[4], pb[4];
#pragma unroll
    for (int i = 0; i < 4; i++) pa[i] = A[(m0 + ra + 16*i)*K + ca];
#pragma unroll
    for (int i = 0; i < 4; i++) pb[i] = bok ? Bw[(rb + 4*i)*N + n0 + cb] : 0.f;

    for (int kt = 0; kt < K; kt += 16) {
#pragma unroll
        for (int i = 0; i < 4; i++) As[ca][ra + 16*i] = pa[i];
#pragma unroll
        for (int i = 0; i < 4; i++) Bs[rb + 4*i][cb] = pb[i];
        __syncthreads();
        if (kt + 16 < K) {
#pragma unroll
            for (int i = 0; i < 4; i++) pa[i] = A[(m0 + ra + 16*i)*K + kt + 16 + ca];
#pragma unroll
            for (int i = 0; i < 4; i++) pb[i] = bok ? Bw[(kt + 16 + rb + 4*i)*N + n0 + cb] : 0.f;
        }
#pragma unroll
        for (int k = 0; k < 16; k++) {
            float4 a = *(const float4*)&As[k][ty*4];
            float4 b = *(const float4*)&Bs[k][tx*4];
            acc[0][0]+=a.x*b.x; acc[0][1]+=a.x*b.y; acc[0][2]+=a.x*b.z; acc[0][3]+=a.x*b.w;
            acc[1][0]+=a.y*b.x; acc[1][1]+=a.y*b.y; acc[1][2]+=a.y*b.z; acc[1][3]+=a.y*b.w;
            acc[2][0]+=a.z*b.x; acc[2][1]+=a.z*b.y; acc[2][2]+=a.z*b.z; acc[2][3]+=a.z*b.w;
            acc[3][0]+=a.w*b.x; acc[3][1]+=a.w*b.y; acc[3][2]+=a.w*b.z; acc[3][3]+=a.w*b.w;
        }
        __syncthreads();
    }

    if (mode == 0) {
#pragma unroll
        for (int i = 0; i < 4; i++) {
            int row = m0 + ty*4 + i;
#pragma unroll
            for (int j = 0; j < 4; j++) {
                int col = n0 + tx*4 + j;
                if (col < N) g_Z[row*PROJ + col] = acc[i][j];
            }
        }
    } else {
#pragma unroll
        for (int i = 0; i < 4; i++) {
            int row = m0 + ty*4 + i;
            int seq = row / L, t = row - seq*L;
            float* op = xout + xoff(axis, seq, t);
#pragma unroll
            for (int j = 0; j < 4; j++) op[n0 + tx*4 + j] += acc[i][j];
        }
    }
}

/* ------- 3. causal conv(K=4)+SiLU over 640 ch, plus softplus(dt) ------- */
__global__ void k_convdt(const float* __restrict__ Wc, const float* __restrict__ bc,
                         const float* __restrict__ dtb, int L)
{
    int idx = blockIdx.x*256 + threadIdx.x;
    if (idx >= NTOK*(CONVDIM + NHEADS)) return;
    int tok = idx / (CONVDIM + NHEADS);
    int c   = idx - tok*(CONVDIM + NHEADS);
    int seq = tok / L, t = tok - seq*L;
    if (c < CONVDIM) {
        float acc = bc[c];
#pragma unroll
        for (int k = 0; k < 4; k++) {
            int tt = t - 3 + k;
            if (tt >= 0) acc += Wc[c*4 + k] * g_Z[(seq*L + tt)*PROJ + DIN + c];
        }
        g_xBC[tok*CONVDIM + c] = acc / (1.f + __expf(-acc));
    } else {
        int h = c - CONVDIM;
        float v = g_Z[tok*PROJ + DIN + CONVDIM + h] + dtb[h];
        g_dt[tok*NHEADS + h] = (v > 20.f) ? v : log1pf(__expf(v));
    }
}

/* --------- 5. CB stored transposed: g_CB[seq][s][l] = B[s].C[l] -------- */
__global__ void k_cb(int L)
{
    __shared__ __align__(16) float Bt[64][68], Ct[64][68];   /* [n][s], [n][l] */
    int seq = blockIdx.x;
    int s0 = blockIdx.y*64, l0 = blockIdx.z*64;
    int tid = threadIdx.x;
    int n = tid & 63, r = tid >> 6;
#pragma unroll 4
    for (int i = 0; i < 16; i++) {
        int row = r + 4*i;
        int gs = s0 + row, gl = l0 + row;
        Bt[n][row] = (gs < L) ? g_xBC[(seq*L + gs)*CONVDIM + DIN + n]          : 0.f;
        Ct[n][row] = (gl < L) ? g_xBC[(seq*L + gl)*CONVDIM + DIN + DSTATE + n] : 0.f;
    }
    __syncthreads();
    int tx = tid & 15, ty = tid >> 4;
    float acc[4][4] = {};
#pragma unroll 8
    for (int k = 0; k < 64; k++) {
        float4 a = *(const float4*)&Bt[k][ty*4];
        float4 b = *(const float4*)&Ct[k][tx*4];
        acc[0][0]+=a.x*b.x; acc[0][1]+=a.x*b.y; acc[0][2]+=a.x*b.z; acc[0][3]+=a.x*b.w;
        acc[1][0]+=a.y*b.x; acc[1][1]+=a.y*b.y; acc[1][2]+=a.y*b.z; acc[1][3]+=a.y*b.w;
        acc[2][0]+=a.z*b.x; acc[2][1]+=a.z*b.y; acc[2][2]+=a.z*b.z; acc[2][3]+=a.z*b.w;
        acc[3][0]+=a.w*b.x; acc[3][1]+=a.w*b.y; acc[3][2]+=a.w*b.z; acc[3][3]+=a.w*b.w;
    }
#pragma unroll
    for (int i = 0; i < 4; i++) {
        int gs = s0 + ty*4 + i;
#pragma unroll
        for (int j = 0; j < 4; j++) {
            int gl = l0 + tx*4 + j;
            if (gs < L && gl < L) g_CB[(seq*L + gs)*L + gl] = acc[i][j];
        }
    }
}

/* --- 6. SSD: y[l,h,:] = sum_s CB[s,l]*w(l,s,h)*dt[s,h]*xh[s,h,:] -------
 * fwd (s<l: exp(cum[l]-cum[s])) + bwd (s>l: exp((cum[s]-dtA[s])-(cum[l]-dtA[l])))
 * diagonal counted twice. dt*A cumsum computed in-block (Hillis-Steele). */
__global__ void k_ssd(const float* __restrict__ Alog, int L)
{
    __shared__ float cum[192], dts[192];
    __shared__ __align__(16) float Wt[64][68];   /* [s][l] */
    __shared__ __align__(16) float Xs[64][68];   /* [s][p] */
    int seq = blockIdx.x, h = blockIdx.y, l0 = blockIdx.z*64;
    int tid = threadIdx.x;
    float A = -expf(Alog[h]);

    /* block-parallel inclusive scan of dt*A over t in [0,L), L<=192 */
    for (int t = tid; t < L; t += 256) {
        float d = g_dt[(seq*L + t)*NHEADS + h];
        dts[t] = d;
        cum[t] = d*A;
    }
    __syncthreads();
    for (int off = 1; off < L; off <<= 1) {
        float v = 0.f;
        if (tid < L && tid >= off) v = cum[tid - off];
        __syncthreads();
        if (tid < L) cum[tid] += v;
        __syncthreads();
    }

    int tx = tid & 15, ty = tid >> 4;
    int fc = tid & 63, fr = tid >> 6;
    float acc[4][4] = {};

    for (int s0 = 0; s0 < L; s0 += 64) {
#pragma unroll 4
        for (int i = 0; i < 16; i++) {           /* load xh tile */
            int s = fr + 4*i;
            int gs = s0 + s;
            Xs[s][fc] = (gs < L) ? g_xBC[(seq*L + gs)*CONVDIM + h*HEADP + fc] : 0.f;
        }
#pragma unroll 4
        for (int i = 0; i < 16; i++) {           /* build weight tile */
            int sW = fr + 4*i, lW = fc;
            int gs = s0 + sW, gl = l0 + lW;
            float w = 0.f;
            if (gl < L && gs < L) {
                float cb = g_CB[(seq*L + gs)*L + gl];   /* coalesced in lW */
                float e;
                if (gs < gl)       e = __expf(cum[gl] - cum[gs]);
                else if (gs == gl) e = 2.f;
                else               e = __expf((cum[gs] - dts[gs]*A) - (cum[gl] - dts[gl]*A));
                w = cb * e * dts[gs];
            }
            Wt[sW][lW] = w;                      /* conflict-free store */
        }
        __syncthreads();
#pragma unroll 8
        for (int k = 0; k < 64; k++) {
            float4 a = *(const float4*)&Wt[k][ty*4];
            float4 b = *(const float4*)&Xs[k][tx*4];
            acc[0][0]+=a.x*b.x; acc[0][1]+=a.x*b.y; acc[0][2]+=a.x*b.z; acc[0][3]+=a.x*b.w;
            acc[1][0]+=a.y*b.x; acc[1][1]+=a.y*b.y; acc[1][2]+=a.y*b.z; acc[1][3]+=a.y*b.w;
            acc[2][0]+=a.z*b.x; acc[2][1]+=a.z*b.y; acc[2][2]+=a.z*b.z; acc[2][3]+=a.z*b.w;
            acc[3][0]+=a.w*b.x; acc[3][1]+=a.w*b.y; acc[3][2]+=a.w*b.z; acc[3][3]+=a.w*b.w;
        }
        __syncthreads();
    }
#pragma unroll
    for (int i = 0; i < 4; i++) {
        int gl = l0 + ty*4 + i;
        if (gl < L) {
            float* yp = g_y + (seq*L + gl)*DIN + h*HEADP;
#pragma unroll
            for (int j = 0; j < 4; j++) yp[tx*4 + j] = acc[i][j];
        }
    }
}

/* ---------- 7. (y + D*xh) * silu(z), then RMSNorm(512) * gn_w ---------- */
__global__ void k_gate(const float* __restrict__ Dv, const float* __restrict__ gnw)
{
    __shared__ float red[8];
    int tok = blockIdx.x, tid = threadIdx.x;
    float v[2]; float ss = 0.f;
#pragma unroll
    for (int i = 0; i < 2; i++) {
        int d = tid + 256*i;
        float y = g_y[tok*DIN + d] + Dv[d >> 6]*g_xBC[tok*CONVDIM + d];
        float z = g_Z[tok*PROJ + d];
        y *= z / (1.f + __expf(-z));
        v[i] = y; ss += y*y;
    }
#pragma unroll
    for (int o = 16; o; o >>= 1) ss += __shfl_xor_sync(0xffffffffu, ss, o);
    if ((tid & 31) == 0) red[tid >> 5] = ss;
    __syncthreads();
    if (tid < 32) {
        float s = (tid < 8) ? red[tid] : 0.f;
#pragma unroll
        for (int o = 4; o; o >>= 1) s += __shfl_xor_sync(0xffffffffu, s, o);
        if (tid == 0) red[0] = s;
    }
    __syncthreads();
    float r = rsqrtf(red[0]*(1.f/DIN) + 1e-6f);
#pragma unroll
    for (int i = 0; i < 2; i++) {
        int d = tid + 256*i;
        g_y[tok*DIN + d] = v[i]*r*gnw[d];
    }
}

/* ----------------------------- host side ------------------------------ */
static void run_call(float* out, const float* const* P, int li, int axis)
{
    const float* nw   = P[0] + li*HID;
    const float* Win  = P[1] + li*HID*PROJ;
    const float* Wc   = P[2] + li*CONVDIM*4;
    const float* bc   = P[3] + li*CONVDIM;
    const float* dtb  = P[4] + li*NHEADS;
    const float* Alog = P[5] + li*NHEADS;
    const float* Dv   = P[6] + li*NHEADS;
    const float* gnw  = P[7] + li*DIN;
    const float* Wout = P[8] + li*DIN*HID;
    int L = (axis == 0) ? Tn : NBn;
    int nseq = NTOK / L;
    int lt = (L + 63)/64;

    k_rmsnorm<<<NTOK/8, 256>>>(out, nw, axis, L);
    k_sgemm<<<dim3((PROJ + 63)/64, NTOK/64), 256>>>(0, Win, PROJ, HID, 0, nullptr, axis, L);
    k_convdt<<<(NTOK*(CONVDIM + NHEADS) + 255)/256, 256>>>(Wc, bc, dtb, L);
    k_cb<<<dim3(nseq, lt, lt), 256>>>(L);
    k_ssd<<<dim3(nseq, NHEADS, lt), 256>>>(Alog, L);
    k_gate<<<NTOK, 256>>>(Dv, gnw);
    k_sgemm<<<dim3(HID/64, NTOK/64), 256>>>(1, Wout, HID, DIN, 1, out, axis, L);
}

extern "C" void kernel_launch(void* const* d_in, const int* in_sizes, int n_in,
                              void* d_out, int out_size)
{
    float* out = (float*)d_out;
    cudaMemcpyAsync(out, d_in[0], (size_t)out_size*sizeof(float),
                    cudaMemcpyDeviceToDevice);
    const float* tp[9]; const float* bp[9];
    for (int i = 0; i < 9; i++) {
        tp[i] = (const float*)d_in[1 + i];
        bp[i] = (const float*)d_in[10 + i];
    }
    for (int li = 0; li < 2; li++) {
        run_call(out, tp, li, 0);   /* time axis   */
        run_call(out, bp, li, 1);   /* block axis  */
    }
}

// round 3
// speedup vs baseline: 1.1895x; 1.1310x over previous
#include <cuda_runtime.h>
#include <math.h>

#define Bn 2
#define Tn 192
#define NBn 62
#define HID 256
#define DIN 512
#define NHEADS 8
#define HEADP 64
#define DSTATE 64
#define CONVDIM 640
#define PROJ 1160
#define NTOK (Bn*Tn*NBn)          /* 23808 */
#define CBMAX (124*192*192)       /* t-axis CB scratch is the max */

/* ------------ device-global scratch (no cudaMalloc allowed) ------------ */
__device__ float g_xn [NTOK*HID];        /* rmsnorm'd input, [tok,256]   */
__device__ float g_Z  [NTOK*PROJ];       /* in-proj output,  [tok,1160]  */
__device__ float g_xBC[NTOK*CONVDIM];    /* conv+silu,       [tok,640]   */
__device__ float g_dt [NTOK*NHEADS];     /* softplus dt,     [tok,8]     */
__device__ float g_CB [CBMAX];           /* B.C^T scores, [seq,s,l]      */
__device__ float g_y  [NTOK*DIN];        /* ssd out / gated, [tok,512]   */

/* token (seq,t) -> offset into the (B,T,NB,H) activation tensor */
__device__ __forceinline__ int xoff(int axis, int seq, int t)
{
    if (axis == 0) {                       /* t-axis: seq=(b,nb), pos=t  */
        int b = seq / NBn, nb = seq - b*NBn;
        return ((b*Tn + t)*NBn + nb)*HID;
    }
    return (seq*NBn + t)*HID;              /* b-axis: contiguous          */
}

/* ------------------ 1. strided gather + RMSNorm(256) ------------------ */
__global__ void k_rmsnorm(const float* __restrict__ x, const float* __restrict__ w,
                          int axis, int L)
{
    int tok = blockIdx.x*8 + (threadIdx.x >> 5);
    if (tok >= NTOK) return;
    int lane = threadIdx.x & 31;
    int seq = tok / L, t = tok - seq*L;
    const float* xp = x + xoff(axis, seq, t);
    float v[8]; float ss = 0.f;
#pragma unroll
    for (int i = 0; i < 8; i++) { v[i] = xp[lane + 32*i]; ss += v[i]*v[i]; }
#pragma unroll
    for (int o = 16; o; o >>= 1) ss += __shfl_xor_sync(0xffffffffu, ss, o);
    float r = rsqrtf(ss*(1.f/HID) + 1e-6f);
    float* op = g_xn + tok*HID;
#pragma unroll
    for (int i = 0; i < 8; i++) op[lane + 32*i] = v[i]*r*w[lane + 32*i];
}

/* ------ 2/8. SGEMM 128x64x16 tiles, 8x4 micro-tile, prefetched -------- */
/* asel: 0 -> A=g_xn (K=256), 1 -> A=g_y (K=512)                          */
/* mode: 0 -> write g_Z[row*PROJ+col]; 1 -> residual scatter-add into x   */
__global__ void __launch_bounds__(256)
k_sgemm(int asel, const float* __restrict__ Bw,
        int N, int K, int mode, float* xout, int axis, int L)
{
    __shared__ __align__(16) float As[16][132];   /* [k][m] */
    __shared__ __align__(16) float Bs[16][64];    /* [k][n] */
    int m0 = blockIdx.y*128, n0 = blockIdx.x*64;
    int tid = threadIdx.x;
    int tx = tid & 15, ty = tid >> 4;
    const float* A = asel ? g_y : g_xn;
    float acc[8][4] = {};
    int ra = tid >> 2, ca = (tid & 3)*4;    /* A loader: rows ra,ra+64; k-cols ca..ca+3 */
    int rb = tid >> 4, cbv = (tid & 15)*4;  /* B loader: 16 rows, vec4 cols */
    int bok = (n0 + cbv) < N;               /* N%4==0 -> all-or-nothing */

    float4 pa0, pa1, pb;
    pa0 = *(const float4*)&A[(m0 + ra     )*K + ca];
    pa1 = *(const float4*)&A[(m0 + ra + 64)*K + ca];
    pb  = bok ? *(const float4*)&Bw[rb*N + n0 + cbv] : make_float4(0,0,0,0);

    for (int kt = 0; kt < K; kt += 16) {
        As[ca+0][ra] = pa0.x; As[ca+1][ra] = pa0.y;
        As[ca+2][ra] = pa0.z; As[ca+3][ra] = pa0.w;
        As[ca+0][ra+64] = pa1.x; As[ca+1][ra+64] = pa1.y;
        As[ca+2][ra+64] = pa1.z; As[ca+3][ra+64] = pa1.w;
        *(float4*)&Bs[rb][cbv] = pb;
        __syncthreads();
        if (kt + 16 < K) {
            pa0 = *(const float4*)&A[(m0 + ra     )*K + kt + 16 + ca];
            pa1 = *(const float4*)&A[(m0 + ra + 64)*K + kt + 16 + ca];
            pb  = bok ? *(const float4*)&Bw[(kt + 16 + rb)*N + n0 + cbv]
                      : make_float4(0,0,0,0);
        }
#pragma unroll
        for (int k = 0; k < 16; k++) {
            float4 a0 = *(const float4*)&As[k][ty*8];
            float4 a1 = *(const float4*)&As[k][ty*8 + 4];
            float4 b  = *(const float4*)&Bs[k][tx*4];
            acc[0][0]+=a0.x*b.x; acc[0][1]+=a0.x*b.y; acc[0][2]+=a0.x*b.z; acc[0][3]+=a0.x*b.w;
            acc[1][0]+=a0.y*b.x; acc[1][1]+=a0.y*b.y; acc[1][2]+=a0.y*b.z; acc[1][3]+=a0.y*b.w;
            acc[2][0]+=a0.z*b.x; acc[2][1]+=a0.z*b.y; acc[2][2]+=a0.z*b.z; acc[2][3]+=a0.z*b.w;
            acc[3][0]+=a0.w*b.x; acc[3][1]+=a0.w*b.y; acc[3][2]+=a0.w*b.z; acc[3][3]+=a0.w*b.w;
            acc[4][0]+=a1.x*b.x; acc[4][1]+=a1.x*b.y; acc[4][2]+=a1.x*b.z; acc[4][3]+=a1.x*b.w;
            acc[5][0]+=a1.y*b.x; acc[5][1]+=a1.y*b.y; acc[5][2]+=a1.y*b.z; acc[5][3]+=a1.y*b.w;
            acc[6][0]+=a1.z*b.x; acc[6][1]+=a1.z*b.y; acc[6][2]+=a1.z*b.z; acc[6][3]+=a1.z*b.w;
            acc[7][0]+=a1.w*b.x; acc[7][1]+=a1.w*b.y; acc[7][2]+=a1.w*b.z; acc[7][3]+=a1.w*b.w;
        }
        __syncthreads();
    }

    int colv = n0 + tx*4;
    if (mode == 0) {
        if (colv < N) {
#pragma unroll
            for (int i = 0; i < 8; i++) {
                int row = m0 + ty*8 + i;
                float4 v = make_float4(acc[i][0], acc[i][1], acc[i][2], acc[i][3]);
                *(float4*)&g_Z[row*PROJ + colv] = v;
            }
        }
    } else {
#pragma unroll
        for (int i = 0; i < 8; i++) {
            int row = m0 + ty*8 + i;
            int seq = row / L, t = row - seq*L;
            float* op = xout + xoff(axis, seq, t) + colv;
            float4 o = *(const float4*)op;
            o.x += acc[i][0]; o.y += acc[i][1]; o.z += acc[i][2]; o.w += acc[i][3];
            *(float4*)op = o;
        }
    }
}

/* ------- 3. causal conv(K=4)+SiLU over 640 ch, plus softplus(dt) ------- */
__global__ void k_convdt(const float* __restrict__ Wc, const float* __restrict__ bc,
                         const float* __restrict__ dtb, int L)
{
    int idx = blockIdx.x*256 + threadIdx.x;
    if (idx >= NTOK*(CONVDIM + NHEADS)) return;
    int tok = idx / (CONVDIM + NHEADS);
    int c   = idx - tok*(CONVDIM + NHEADS);
    int seq = tok / L, t = tok - seq*L;
    if (c < CONVDIM) {
        float acc = bc[c];
#pragma unroll
        for (int k = 0; k < 4; k++) {
            int tt = t - 3 + k;
            if (tt >= 0) acc += Wc[c*4 + k] * g_Z[(seq*L + tt)*PROJ + DIN + c];
        }
        g_xBC[tok*CONVDIM + c] = acc / (1.f + __expf(-acc));
    } else {
        int h = c - CONVDIM;
        float v = g_Z[tok*PROJ + DIN + CONVDIM + h] + dtb[h];
        g_dt[tok*NHEADS + h] = (v > 20.f) ? v : log1pf(__expf(v));
    }
}

/* --------- 5. CB stored transposed: g_CB[seq][s][l] = B[s].C[l] -------- */
__global__ void k_cb(int L)
{
    __shared__ __align__(16) float Bt[64][68], Ct[64][68];   /* [n][s], [n][l] */
    int seq = blockIdx.x;
    int s0 = blockIdx.y*64, l0 = blockIdx.z*64;
    int tid = threadIdx.x;
    int n = tid & 63, r = tid >> 6;
#pragma unroll 4
    for (int i = 0; i < 16; i++) {
        int row = r + 4*i;
        int gs = s0 + row, gl = l0 + row;
        Bt[n][row] = (gs < L) ? g_xBC[(seq*L + gs)*CONVDIM + DIN + n]          : 0.f;
        Ct[n][row] = (gl < L) ? g_xBC[(seq*L + gl)*CONVDIM + DIN + DSTATE + n] : 0.f;
    }
    __syncthreads();
    int tx = tid & 15, ty = tid >> 4;
    float acc[4][4] = {};
#pragma unroll 8
    for (int k = 0; k < 64; k++) {
        float4 a = *(const float4*)&Bt[k][ty*4];
        float4 b = *(const float4*)&Ct[k][tx*4];
        acc[0][0]+=a.x*b.x; acc[0][1]+=a.x*b.y; acc[0][2]+=a.x*b.z; acc[0][3]+=a.x*b.w;
        acc[1][0]+=a.y*b.x; acc[1][1]+=a.y*b.y; acc[1][2]+=a.y*b.z; acc[1][3]+=a.y*b.w;
        acc[2][0]+=a.z*b.x; acc[2][1]+=a.z*b.y; acc[2][2]+=a.z*b.z; acc[2][3]+=a.z*b.w;
        acc[3][0]+=a.w*b.x; acc[3][1]+=a.w*b.y; acc[3][2]+=a.w*b.z; acc[3][3]+=a.w*b.w;
    }
#pragma unroll
    for (int i = 0; i < 4; i++) {
        int gs = s0 + ty*4 + i;
#pragma unroll
        for (int j = 0; j < 4; j++) {
            int gl = l0 + tx*4 + j;
            if (gs < L && gl < L) g_CB[(seq*L + gs)*L + gl] = acc[i][j];
        }
    }
}

/* --- 6. SSD: y[l,h,:] = sum_s CB[s,l]*w(l,s,h)*dt[s,h]*xh[s,h,:] -------
 * fwd (s<l: exp(cum[l]-cum[s])) + bwd (s>l: exp((cum[s]-dtA[s])-(cum[l]-dtA[l])))
 * diagonal counted twice. dt*A cumsum computed in-block (Hillis-Steele). */
__global__ void k_ssd(const float* __restrict__ Alog, int L)
{
    __shared__ float cum[192], dts[192];
    __shared__ __align__(16) float Wt[64][68];   /* [s][l] */
    __shared__ __align__(16) float Xs[64][68];   /* [s][p] */
    int seq = blockIdx.x, h = blockIdx.y, l0 = blockIdx.z*64;
    int tid = threadIdx.x;
    float A = -expf(Alog[h]);

    /* block-parallel inclusive scan of dt*A over t in [0,L), L<=192 */
    for (int t = tid; t < L; t += 256) {
        float d = g_dt[(seq*L + t)*NHEADS + h];
        dts[t] = d;
        cum[t] = d*A;
    }
    __syncthreads();
    for (int off = 1; off < L; off <<= 1) {
        float v = 0.f;
        if (tid < L && tid >= off) v = cum[tid - off];
        __syncthreads();
        if (tid < L) cum[tid] += v;
        __syncthreads();
    }

    int tx = tid & 15, ty = tid >> 4;
    int fc = tid & 63, fr = tid >> 6;
    float acc[4][4] = {};

    for (int s0 = 0; s0 < L; s0 += 64) {
#pragma unroll 4
        for (int i = 0; i < 16; i++) {           /* load xh tile */
            int s = fr + 4*i;
            int gs = s0 + s;
            Xs[s][fc] = (gs < L) ? g_xBC[(seq*L + gs)*CONVDIM + h*HEADP + fc] : 0.f;
        }
#pragma unroll 4
        for (int i = 0; i < 16; i++) {           /* build weight tile */
            int sW = fr + 4*i, lW = fc;
            int gs = s0 + sW, gl = l0 + lW;
            float w = 0.f;
            if (gl < L && gs < L) {
                float cb = g_CB[(seq*L + gs)*L + gl];   /* coalesced in lW */
                float e;
                if (gs < gl)       e = __expf(cum[gl] - cum[gs]);
                else if (gs == gl) e = 2.f;
                else               e = __expf((cum[gs] - dts[gs]*A) - (cum[gl] - dts[gl]*A));
                w = cb * e * dts[gs];
            }
            Wt[sW][lW] = w;                      /* conflict-free store */
        }
        __syncthreads();
#pragma unroll 8
        for (int k = 0; k < 64; k++) {
            float4 a = *(const float4*)&Wt[k][ty*4];
            float4 b = *(const float4*)&Xs[k][tx*4];
            acc[0][0]+=a.x*b.x; acc[0][1]+=a.x*b.y; acc[0][2]+=a.x*b.z; acc[0][3]+=a.x*b.w;
            acc[1][0]+=a.y*b.x; acc[1][1]+=a.y*b.y; acc[1][2]+=a.y*b.z; acc[1][3]+=a.y*b.w;
            acc[2][0]+=a.z*b.x; acc[2][1]+=a.z*b.y; acc[2][2]+=a.z*b.z; acc[2][3]+=a.z*b.w;
            acc[3][0]+=a.w*b.x; acc[3][1]+=a.w*b.y; acc[3][2]+=a.w*b.z; acc[3][3]+=a.w*b.w;
        }
        __syncthreads();
    }
#pragma unroll
    for (int i = 0; i < 4; i++) {
        int gl = l0 + ty*4 + i;
        if (gl < L) {
            float* yp = g_y + (seq*L + gl)*DIN + h*HEADP;
#pragma unroll
            for (int j = 0; j < 4; j++) yp[tx*4 + j] = acc[i][j];
        }
    }
}

/* ---------- 7. (y + D*xh) * silu(z), then RMSNorm(512) * gn_w ---------- */
__global__ void k_gate(const float* __restrict__ Dv, const float* __restrict__ gnw)
{
    __shared__ float red[8];
    int tok = blockIdx.x, tid = threadIdx.x;
    float v[2]; float ss = 0.f;
#pragma unroll
    for (int i = 0; i < 2; i++) {
        int d = tid + 256*i;
        float y = g_y[tok*DIN + d] + Dv[d >> 6]*g_xBC[tok*CONVDIM + d];
        float z = g_Z[tok*PROJ + d];
        y *= z / (1.f + __expf(-z));
        v[i] = y; ss += y*y;
    }
#pragma unroll
    for (int o = 16; o; o >>= 1) ss += __shfl_xor_sync(0xffffffffu, ss, o);
    if ((tid & 31) == 0) red[tid >> 5] = ss;
    __syncthreads();
    if (tid < 32) {
        float s = (tid < 8) ? red[tid] : 0.f;
#pragma unroll
        for (int o = 4; o; o >>= 1) s += __shfl_xor_sync(0xffffffffu, s, o);
        if (tid == 0) red[0] = s;
    }
    __syncthreads();
    float r = rsqrtf(red[0]*(1.f/DIN) + 1e-6f);
#pragma unroll
    for (int i = 0; i < 2; i++) {
        int d = tid + 256*i;
        g_y[tok*DIN + d] = v[i]*r*gnw[d];
    }
}

/* ----------------------------- host side ------------------------------ */
static void run_call(float* out, const float* const* P, int li, int axis)
{
    const float* nw   = P[0] + li*HID;
    const float* Win  = P[1] + li*HID*PROJ;
    const float* Wc   = P[2] + li*CONVDIM*4;
    const float* bc   = P[3] + li*CONVDIM;
    const float* dtb  = P[4] + li*NHEADS;
    const float* Alog = P[5] + li*NHEADS;
    const float* Dv   = P[6] + li*NHEADS;
    const float* gnw  = P[7] + li*DIN;
    const float* Wout = P[8] + li*DIN*HID;
    int L = (axis == 0) ? Tn : NBn;
    int nseq = NTOK / L;
    int lt = (L + 63)/64;

    k_rmsnorm<<<NTOK/8, 256>>>(out, nw, axis, L);
    k_sgemm<<<dim3((PROJ + 63)/64, NTOK/128), 256>>>(0, Win, PROJ, HID, 0, nullptr, axis, L);
    k_convdt<<<(NTOK*(CONVDIM + NHEADS) + 255)/256, 256>>>(Wc, bc, dtb, L);
    k_cb<<<dim3(nseq, lt, lt), 256>>>(L);
    k_ssd<<<dim3(nseq, NHEADS, lt), 256>>>(Alog, L);
    k_gate<<<NTOK, 256>>>(Dv, gnw);
    k_sgemm<<<dim3(HID/64, NTOK/128), 256>>>(1, Wout, HID, DIN, 1, out, axis, L);
}

extern "C" void kernel_launch(void* const* d_in, const int* in_sizes, int n_in,
                              void* d_out, int out_size)
{
    float* out = (float*)d_out;
    cudaMemcpyAsync(out, d_in[0], (size_t)out_size*sizeof(float),
                    cudaMemcpyDeviceToDevice);
    const float* tp[9]; const float* bp[9];
    for (int i = 0; i < 9; i++) {
        tp[i] = (const float*)d_in[1 + i];
        bp[i] = (const float*)d_in[10 + i];
    }
    for (int li = 0; li < 2; li++) {
        run_call(out, tp, li, 0);   /* time axis   */
        run_call(out, bp, li, 1);   /* block axis  */
    }
}

// round 5
// speedup vs baseline: 1.3126x; 1.1035x over previous
#include <cuda_runtime.h>
#include <math.h>
#include <stdint.h>

#define Bn 2
#define Tn 192
#define NBn 62
#define HID 256
#define DIN 512
#define NHEADS 8
#define HEADP 64
#define DSTATE 64
#define CONVDIM 640
#define PROJ 1160
#define NTOK (Bn*Tn*NBn)          /* 23808 */
#define CBMAX (124*192*192)

/* ------------ device-global scratch (no cudaMalloc allowed) ------------ */
__device__ float g_xn [NTOK*HID];
__device__ float g_Z  [NTOK*PROJ];
__device__ float g_xBC[NTOK*CONVDIM];
__device__ float g_dt [NTOK*NHEADS];
__device__ float g_CB [CBMAX];
__device__ float g_y  [NTOK*DIN];
__device__ float g_WinT [4*PROJ*HID];    /* Win^T  [N=1160][K=256] per (axis,layer) */
__device__ float g_WoutT[4*HID*DIN];     /* Wout^T [N=256][K=512]                    */

/* token (seq,t) -> offset into the (B,T,NB,H) activation tensor */
__device__ __forceinline__ int xoff(int axis, int seq, int t)
{
    if (axis == 0) {
        int b = seq / NBn, nb = seq - b*NBn;
        return ((b*Tn + t)*NBn + nb)*HID;
    }
    return (seq*NBn + t)*HID;
}

__device__ __forceinline__ float tf32rn(float x)
{
    uint32_t u; asm("cvt.rn.tf32.f32 %0, %1;" : "=r"(u) : "f"(x));
    return __uint_as_float(u);
}
__device__ __forceinline__ void mma8(float* d, const uint32_t* a,
                                     uint32_t b0, uint32_t b1)
{
    asm volatile("mma.sync.aligned.m16n8k8.row.col.f32.tf32.tf32.f32 "
        "{%0,%1,%2,%3}, {%4,%5,%6,%7}, {%8,%9}, {%0,%1,%2,%3};"
        : "+f"(d[0]), "+f"(d[1]), "+f"(d[2]), "+f"(d[3])
        : "r"(a[0]), "r"(a[1]), "r"(a[2]), "r"(a[3]), "r"(b0), "r"(b1));
}

/* ------------------ 1. strided gather + RMSNorm(256) ------------------ */
__global__ void k_rmsnorm(const float* __restrict__ x, const float* __restrict__ w,
                          int axis, int L)
{
    int tok = blockIdx.x*8 + (threadIdx.x >> 5);
    if (tok >= NTOK) return;
    int lane = threadIdx.x & 31;
    int seq = tok / L, t = tok - seq*L;
    const float* xp = x + xoff(axis, seq, t);
    float v[8]; float ss = 0.f;
#pragma unroll
    for (int i = 0; i < 8; i++) { v[i] = xp[lane + 32*i]; ss += v[i]*v[i]; }
#pragma unroll
    for (int o = 16; o; o >>= 1) ss += __shfl_xor_sync(0xffffffffu, ss, o);
    float r = rsqrtf(ss*(1.f/HID) + 1e-6f);
    float* op = g_xn + tok*HID;
#pragma unroll
    for (int i = 0; i < 8; i++) op[lane + 32*i] = v[i]*r*w[lane + 32*i];
}

/* -------- weight transpose: W[K][N] -> WT[N][K] (run once/launch) ------ */
__global__ void k_transpose(const float* __restrict__ W, float* __restrict__ WT,
                            int K, int N)
{
    __shared__ float t[32][33];
    int n0 = blockIdx.x*32, k0 = blockIdx.y*32;
    int x = threadIdx.x, y = threadIdx.y;
#pragma unroll
    for (int i = 0; i < 32; i += 8) {
        int k = k0 + y + i, n = n0 + x;
        t[y+i][x] = (k < K && n < N) ? W[k*N + n] : 0.f;
    }
    __syncthreads();
#pragma unroll
    for (int i = 0; i < 32; i += 8) {
        int n = n0 + y + i, k = k0 + x;
        if (n < N && k < K) WT[n*K + k] = t[x][y+i];
    }
}

/* ---- 2/8. HMMA tf32 split GEMM: D[128,128] = A[128,K] * Wt[N,K]^T -----
 * split-precision: x = hi + lo (tf32 RN split, done once at smem store);
 * D = Ah*Bh + Ah*Bl + Al*Bh via mma.sync m16n8k8 tf32 (~fp32 accuracy).
 * Block 128x128, 8 warps (4m x 2n), warp tile 32x64, K-chunks of 32.
 * mode 0: write g_Z[row*PROJ+col]; mode 1: residual add into xout.      */
#define SA 36                      /* smem row stride (floats), conflict-free */
__global__ void __launch_bounds__(256)
k_mma(int asel, const float* __restrict__ Wt, int N, int K,
      int mode, float* xout, int axis, int L)
{
    extern __shared__ float sm[];
    float* Ahi = sm;
    float* Alo = sm + 128*SA;
    float* Bhi = sm + 2*128*SA;
    float* Blo = sm + 3*128*SA;
    const float* A = asel ? g_y : g_xn;
    int m0 = blockIdx.y*128, n0 = blockIdx.x*128;
    int tid = threadIdx.x, lane = tid & 31, wid = tid >> 5;
    int wm = (wid & 3)*32, wn = (wid >> 2)*64;
    int row0 = tid >> 3, c4 = (tid & 7)*4;

    float acc[2][8][4];
#pragma unroll
    for (int mi = 0; mi < 2; mi++)
#pragma unroll
        for (int ni = 0; ni < 8; ni++)
#pragma unroll
            for (int q = 0; q < 4; q++) acc[mi][ni][q] = 0.f;

    int nch = K >> 5;
    float4 pa[4], pb[4];
#pragma unroll
    for (int i = 0; i < 4; i++)
        pa[i] = *(const float4*)&A[(size_t)(m0 + row0 + 32*i)*K + c4];
#pragma unroll
    for (int i = 0; i < 4; i++)
        pb[i] = (n0 + row0 + 32*i < N)
              ? *(const float4*)&Wt[(size_t)(n0 + row0 + 32*i)*K + c4]
              : make_float4(0.f,0.f,0.f,0.f);

    for (int c = 0; c < nch; c++) {
#pragma unroll
        for (int i = 0; i < 4; i++) {
            int r = row0 + 32*i;
            float4 v = pa[i], h, l;
            h.x = tf32rn(v.x); l.x = tf32rn(v.x - h.x);
            h.y = tf32rn(v.y); l.y = tf32rn(v.y - h.y);
            h.z = tf32rn(v.z); l.z = tf32rn(v.z - h.z);
            h.w = tf32rn(v.w); l.w = tf32rn(v.w - h.w);
            *(float4*)&Ahi[r*SA + c4] = h;
            *(float4*)&Alo[r*SA + c4] = l;
            v = pb[i];
            h.x = tf32rn(v.x); l.x = tf32rn(v.x - h.x);
            h.y = tf32rn(v.y); l.y = tf32rn(v.y - h.y);
            h.z = tf32rn(v.z); l.z = tf32rn(v.z - h.z);
            h.w = tf32rn(v.w); l.w = tf32rn(v.w - h.w);
            *(float4*)&Bhi[r*SA + c4] = h;
            *(float4*)&Blo[r*SA + c4] = l;
        }
        __syncthreads();
        if (c + 1 < nch) {
            int kt = (c+1)*32;
#pragma unroll
            for (int i = 0; i < 4; i++)
                pa[i] = *(const float4*)&A[(size_t)(m0 + row0 + 32*i)*K + kt + c4];
#pragma unroll
            for (int i = 0; i < 4; i++)
                pb[i] = (n0 + row0 + 32*i < N)
                      ? *(const float4*)&Wt[(size_t)(n0 + row0 + 32*i)*K + kt + c4]
                      : make_float4(0.f,0.f,0.f,0.f);
        }
#pragma unroll
        for (int k8 = 0; k8 < 4; k8++) {
            int kk = k8*8 + (lane & 3);
            int r  = lane >> 2;
            uint32_t ah[2][4], al[2][4];
#pragma unroll
            for (int mi = 0; mi < 2; mi++) {
                int rb = wm + mi*16;
                ah[mi][0] = __float_as_uint(Ahi[(rb + r    )*SA + kk]);
                ah[mi][1] = __float_as_uint(Ahi[(rb + r + 8)*SA + kk]);
                ah[mi][2] = __float_as_uint(Ahi[(rb + r    )*SA + kk + 4]);
                ah[mi][3] = __float_as_uint(Ahi[(rb + r + 8)*SA + kk + 4]);
                al[mi][0] = __float_as_uint(Alo[(rb + r    )*SA + kk]);
                al[mi][1] = __float_as_uint(Alo[(rb + r + 8)*SA + kk]);
                al[mi][2] = __float_as_uint(Alo[(rb + r    )*SA + kk + 4]);
                al[mi][3] = __float_as_uint(Alo[(rb + r + 8)*SA + kk + 4]);
            }
#pragma unroll
            for (int ni = 0; ni < 8; ni++) {
                int nb = (wn + ni*8 + r)*SA + k8*8 + (lane & 3);
                uint32_t bh0 = __float_as_uint(Bhi[nb]);
                uint32_t bh1 = __float_as_uint(Bhi[nb + 4]);
                uint32_t bl0 = __float_as_uint(Blo[nb]);
                uint32_t bl1 = __float_as_uint(Blo[nb + 4]);
#pragma unroll
                for (int mi = 0; mi < 2; mi++) {
                    mma8(acc[mi][ni], ah[mi], bh0, bh1);
                    mma8(acc[mi][ni], ah[mi], bl0, bl1);
                    mma8(acc[mi][ni], al[mi], bh0, bh1);
                }
            }
        }
        __syncthreads();
    }

    /* epilogue: stage through smem for coalesced global access */
    float (*S)[132] = (float(*)[132])sm;   /* 128*132*4 = 67584 <= 73728 */
#pragma unroll
    for (int mi = 0; mi < 2; mi++)
#pragma unroll
        for (int ni = 0; ni < 8; ni++) {
            int r   = wm + mi*16 + (lane >> 2);
            int col = wn + ni*8 + (lane & 3)*2;
            S[r    ][col] = acc[mi][ni][0]; S[r    ][col+1] = acc[mi][ni][1];
            S[r + 8][col] = acc[mi][ni][2]; S[r + 8][col+1] = acc[mi][ni][3];
        }
    __syncthreads();
    int rr = tid >> 1, cb = (tid & 1)*64;
    if (mode == 0) {
        float* zp = g_Z + (size_t)(m0 + rr)*PROJ + n0 + cb;
#pragma unroll
        for (int j = 0; j < 16; j++) {
            if (n0 + cb + j*4 < N)
                *(float4*)&zp[j*4] = *(const float4*)&S[rr][cb + j*4];
        }
    } else {
        int row = m0 + rr;
        int seq = row / L, t = row - seq*L;
        float* op = xout + xoff(axis, seq, t) + n0 + cb;
#pragma unroll
        for (int j = 0; j < 16; j++) {
            float4 o = *(const float4*)&op[j*4];
            const float4 v = *(const float4*)&S[rr][cb + j*4];
            o.x += v.x; o.y += v.y; o.z += v.z; o.w += v.w;
            *(float4*)&op[j*4] = o;
        }
    }
}
#define GSM (4*128*SA*4)

/* ------- 3. causal conv(K=4)+SiLU over 640 ch, plus softplus(dt) ------- */
__global__ void k_convdt(const float* __restrict__ Wc, const float* __restrict__ bc,
                         const float* __restrict__ dtb, int L)
{
    int idx = blockIdx.x*256 + threadIdx.x;
    if (idx >= NTOK*(CONVDIM + NHEADS)) return;
    int tok = idx / (CONVDIM + NHEADS);
    int c   = idx - tok*(CONVDIM + NHEADS);
    int seq = tok / L, t = tok - seq*L;
    if (c < CONVDIM) {
        float acc = bc[c];
#pragma unroll
        for (int k = 0; k < 4; k++) {
            int tt = t - 3 + k;
            if (tt >= 0) acc += Wc[c*4 + k] * g_Z[(size_t)(seq*L + tt)*PROJ + DIN + c];
        }
        g_xBC[(size_t)tok*CONVDIM + c] = acc / (1.f + __expf(-acc));
    } else {
        int h = c - CONVDIM;
        float v = g_Z[(size_t)tok*PROJ + DIN + CONVDIM + h] + dtb[h];
        g_dt[tok*NHEADS + h] = (v > 20.f) ? v : log1pf(__expf(v));
    }
}

/* --------- 5. CB stored transposed: g_CB[seq][s][l] = B[s].C[l] -------- */
__global__ void k_cb(int L)
{
    __shared__ __align__(16) float Bt[64][68], Ct[64][68];
    int seq = blockIdx.x;
    int s0 = blockIdx.y*64, l0 = blockIdx.z*64;
    int tid = threadIdx.x;
    int n = tid & 63, r = tid >> 6;
#pragma unroll 4
    for (int i = 0; i < 16; i++) {
        int row = r + 4*i;
        int gs = s0 + row, gl = l0 + row;
        Bt[n][row] = (gs < L) ? g_xBC[(size_t)(seq*L + gs)*CONVDIM + DIN + n]          : 0.f;
        Ct[n][row] = (gl < L) ? g_xBC[(size_t)(seq*L + gl)*CONVDIM + DIN + DSTATE + n] : 0.f;
    }
    __syncthreads();
    int tx = tid & 15, ty = tid >> 4;
    float acc[4][4] = {};
#pragma unroll 8
    for (int k = 0; k < 64; k++) {
        float4 a = *(const float4*)&Bt[k][ty*4];
        float4 b = *(const float4*)&Ct[k][tx*4];
        acc[0][0]+=a.x*b.x; acc[0][1]+=a.x*b.y; acc[0][2]+=a.x*b.z; acc[0][3]+=a.x*b.w;
        acc[1][0]+=a.y*b.x; acc[1][1]+=a.y*b.y; acc[1][2]+=a.y*b.z; acc[1][3]+=a.y*b.w;
        acc[2][0]+=a.z*b.x; acc[2][1]+=a.z*b.y; acc[2][2]+=a.z*b.z; acc[2][3]+=a.z*b.w;
        acc[3][0]+=a.w*b.x; acc[3][1]+=a.w*b.y; acc[3][2]+=a.w*b.z; acc[3][3]+=a.w*b.w;
    }
#pragma unroll
    for (int i = 0; i < 4; i++) {
        int gs = s0 + ty*4 + i;
#pragma unroll
        for (int j = 0; j < 4; j++) {
            int gl = l0 + tx*4 + j;
            if (gs < L && gl < L) g_CB[(size_t)(seq*L + gs)*L + gl] = acc[i][j];
        }
    }
}

/* --- 6. SSD with in-block cumsum (fwd+bwd combined, diagonal x2) ------- */
__global__ void k_ssd(const float* __restrict__ Alog, int L)
{
    __shared__ float cum[192], dts[192];
    __shared__ __align__(16) float Wt[64][68];
    __shared__ __align__(16) float Xs[64][68];
    int seq = blockIdx.x, h = blockIdx.y, l0 = blockIdx.z*64;
    int tid = threadIdx.x;
    float A = -expf(Alog[h]);

    for (int t = tid; t < L; t += 256) {
        float d = g_dt[(seq*L + t)*NHEADS + h];
        dts[t] = d;
        cum[t] = d*A;
    }
    __syncthreads();
    for (int off = 1; off < L; off <<= 1) {
        float v = 0.f;
        if (tid < L && tid >= off) v = cum[tid - off];
        __syncthreads();
        if (tid < L) cum[tid] += v;
        __syncthreads();
    }

    int tx = tid & 15, ty = tid >> 4;
    int fc = tid & 63, fr = tid >> 6;
    float acc[4][4] = {};

    for (int s0 = 0; s0 < L; s0 += 64) {
#pragma unroll 4
        for (int i = 0; i < 16; i++) {
            int s = fr + 4*i;
            int gs = s0 + s;
            Xs[s][fc] = (gs < L) ? g_xBC[(size_t)(seq*L + gs)*CONVDIM + h*HEADP + fc] : 0.f;
        }
#pragma unroll 4
        for (int i = 0; i < 16; i++) {
            int sW = fr + 4*i, lW = fc;
            int gs = s0 + sW, gl = l0 + lW;
            float w = 0.f;
            if (gl < L && gs < L) {
                float cb = g_CB[(size_t)(seq*L + gs)*L + gl];
                float e;
                if (gs < gl)       e = __expf(cum[gl] - cum[gs]);
                else if (gs == gl) e = 2.f;
                else               e = __expf((cum[gs] - dts[gs]*A) - (cum[gl] - dts[gl]*A));
                w = cb * e * dts[gs];
            }
            Wt[sW][lW] = w;
        }
        __syncthreads();
#pragma unroll 8
        for (int k = 0; k < 64; k++) {
            float4 a = *(const float4*)&Wt[k][ty*4];
            float4 b = *(const float4*)&Xs[k][tx*4];
            acc[0][0]+=a.x*b.x; acc[0][1]+=a.x*b.y; acc[0][2]+=a.x*b.z; acc[0][3]+=a.x*b.w;
            acc[1][0]+=a.y*b.x; acc[1][1]+=a.y*b.y; acc[1][2]+=a.y*b.z; acc[1][3]+=a.y*b.w;
            acc[2][0]+=a.z*b.x; acc[2][1]+=a.z*b.y; acc[2][2]+=a.z*b.z; acc[2][3]+=a.z*b.w;
            acc[3][0]+=a.w*b.x; acc[3][1]+=a.w*b.y; acc[3][2]+=a.w*b.z; acc[3][3]+=a.w*b.w;
        }
        __syncthreads();
    }
#pragma unroll
    for (int i = 0; i < 4; i++) {
        int gl = l0 + ty*4 + i;
        if (gl < L) {
            float* yp = g_y + (size_t)(seq*L + gl)*DIN + h*HEADP;
#pragma unroll
            for (int j = 0; j < 4; j++) yp[tx*4 + j] = acc[i][j];
        }
    }
}

/* ---------- 7. (y + D*xh) * silu(z), then RMSNorm(512) * gn_w ---------- */
__global__ void k_gate(const float* __restrict__ Dv, const float* __restrict__ gnw)
{
    __shared__ float red[8];
    int tok = blockIdx.x, tid = threadIdx.x;
    float v[2]; float ss = 0.f;
#pragma unroll
    for (int i = 0; i < 2; i++) {
        int d = tid + 256*i;
        float y = g_y[(size_t)tok*DIN + d] + Dv[d >> 6]*g_xBC[(size_t)tok*CONVDIM + d];
        float z = g_Z[(size_t)tok*PROJ + d];
        y *= z / (1.f + __expf(-z));
        v[i] = y; ss += y*y;
    }
#pragma unroll
    for (int o = 16; o; o >>= 1) ss += __shfl_xor_sync(0xffffffffu, ss, o);
    if ((tid & 31) == 0) red[tid >> 5] = ss;
    __syncthreads();
    if (tid < 32) {
        float s = (tid < 8) ? red[tid] : 0.f;
#pragma unroll
        for (int o = 4; o; o >>= 1) s += __shfl_xor_sync(0xffffffffu, s, o);
        if (tid == 0) red[0] = s;
    }
    __syncthreads();
    float r = rsqrtf(red[0]*(1.f/DIN) + 1e-6f);
#pragma unroll
    for (int i = 0; i < 2; i++) {
        int d = tid + 256*i;
        g_y[(size_t)tok*DIN + d] = v[i]*r*gnw[d];
    }
}

/* ----------------------------- host side ------------------------------ */
static void run_call(float* out, const float* const* P,
                     const float* WinT, const float* WoutT, int li, int axis)
{
    const float* nw   = P[0] + li*HID;
    const float* Wc   = P[2] + li*CONVDIM*4;
    const float* bc   = P[3] + li*CONVDIM;
    const float* dtb  = P[4] + li*NHEADS;
    const float* Alog = P[5] + li*NHEADS;
    const float* Dv   = P[6] + li*NHEADS;
    const float* gnw  = P[7] + li*DIN;
    int L = (axis == 0) ? Tn : NBn;
    int nseq = NTOK / L;
    int lt = (L + 63)/64;

    k_rmsnorm<<<NTOK/8, 256>>>(out, nw, axis, L);
    k_mma<<<dim3((PROJ + 127)/128, NTOK/128), 256, GSM>>>(0, WinT, PROJ, HID, 0, nullptr, axis, L);
    k_convdt<<<(NTOK*(CONVDIM + NHEADS) + 255)/256, 256>>>(Wc, bc, dtb, L);
    k_cb<<<dim3(nseq, lt, lt), 256>>>(L);
    k_ssd<<<dim3(nseq, NHEADS, lt), 256>>>(Alog, L);
    k_gate<<<NTOK, 256>>>(Dv, gnw);
    k_mma<<<dim3(HID/128, NTOK/128), 256, GSM>>>(1, WoutT, HID, DIN, 1, out, axis, L);
}

extern "C" void kernel_launch(void* const* d_in, const int* in_sizes, int n_in,
                              void* d_out, int out_size)
{
    static int smem_set = 0;
    if (!smem_set) {
        cudaFuncSetAttribute(k_mma, cudaFuncAttributeMaxDynamicSharedMemorySize, GSM);
        smem_set = 1;
    }

    float* out = (float*)d_out;
    cudaMemcpyAsync(out, d_in[0], (size_t)out_size*sizeof(float),
                    cudaMemcpyDeviceToDevice);
    const float* tp[9]; const float* bp[9];
    for (int i = 0; i < 9; i++) {
        tp[i] = (const float*)d_in[1 + i];
        bp[i] = (const float*)d_in[10 + i];
    }

    float *winT, *woutT;
    cudaGetSymbolAddress((void**)&winT,  g_WinT);
    cudaGetSymbolAddress((void**)&woutT, g_WoutT);

    for (int ax = 0; ax < 2; ax++) {
        const float* const* P = ax ? bp : tp;
        for (int li = 0; li < 2; li++) {
            int idx = ax*2 + li;
            k_transpose<<<dim3((PROJ+31)/32, (HID+31)/32), dim3(32,8)>>>(
                P[1] + li*HID*PROJ, winT + (size_t)idx*PROJ*HID, HID, PROJ);
            k_transpose<<<dim3((HID+31)/32, (DIN+31)/32), dim3(32,8)>>>(
                P[8] + li*DIN*HID, woutT + (size_t)idx*HID*DIN, DIN, HID);
        }
    }

    for (int li = 0; li < 2; li++) {
        run_call(out, tp, winT + (size_t)(0*2+li)*PROJ*HID,
                          woutT + (size_t)(0*2+li)*HID*DIN, li, 0);
        run_call(out, bp, winT + (size_t)(1*2+li)*PROJ*HID,
                          woutT + (size_t)(1*2+li)*HID*DIN, li, 1);
    }
}

// round 7
// speedup vs baseline: 1.6203x; 1.2344x over previous
#include <cuda_runtime.h>
#include <cuda_bf16.h>
#include <math.h>
#include <stdint.h>

#define Bn 2
#define Tn 192
#define NBn 62
#define HID 256
#define DIN 512
#define NHEADS 8
#define HEADP 64
#define DSTATE 64
#define CONVDIM 640
#define PROJ 1160
#define NTOK (Bn*Tn*NBn)          /* 23808 */
#define CBMAX (124*192*192)

/* ------------ device-global scratch (no cudaMalloc allowed) ------------ */
__device__ float g_xn [NTOK*HID];
__device__ float g_Z  [NTOK*PROJ];
__device__ float g_xBC[NTOK*CONVDIM];
__device__ float g_dt [NTOK*NHEADS];
__device__ float g_CB [CBMAX];
__device__ float g_y  [NTOK*DIN];
__device__ float g_WinT [4*PROJ*HID];    /* Win^T  [N=1160][K=256] per (axis,layer) */
__device__ float g_WoutT[4*HID*DIN];     /* Wout^T [N=256][K=512]                    */

/* token (seq,t) -> offset into the (B,T,NB,H) activation tensor */
__device__ __forceinline__ int xoff(int axis, int seq, int t)
{
    if (axis == 0) {
        int b = seq / NBn, nb = seq - b*NBn;
        return ((b*Tn + t)*NBn + nb)*HID;
    }
    return (seq*NBn + t)*HID;
}

__device__ __forceinline__ uint32_t smem_u32(const void* p)
{
    uint32_t a;
    asm("{ .reg .u64 t; cvta.to.shared.u64 t, %1; cvt.u32.u64 %0, t; }" : "=r"(a) : "l"(p));
    return a;
}
/* pack two floats -> bf16x2 (lo = lower half in memory) */
__device__ __forceinline__ uint32_t bfpk(float lo, float hi)
{
    uint32_t r;
    asm("cvt.rn.bf16x2.f32 %0, %1, %2;" : "=r"(r) : "f"(hi), "f"(lo));
    return r;
}
__device__ __forceinline__ void mma16(float* d, const uint32_t* a,
                                      uint32_t b0, uint32_t b1)
{
    asm volatile("mma.sync.aligned.m16n8k16.row.col.f32.bf16.bf16.f32 "
        "{%0,%1,%2,%3}, {%4,%5,%6,%7}, {%8,%9}, {%0,%1,%2,%3};"
        : "+f"(d[0]), "+f"(d[1]), "+f"(d[2]), "+f"(d[3])
        : "r"(a[0]), "r"(a[1]), "r"(a[2]), "r"(a[3]), "r"(b0), "r"(b1));
}
__device__ __forceinline__ void ldm4(uint32_t* r, uint32_t a)
{
    asm volatile("ldmatrix.sync.aligned.m8n8.x4.shared.b16 {%0,%1,%2,%3}, [%4];"
        : "=r"(r[0]), "=r"(r[1]), "=r"(r[2]), "=r"(r[3]) : "r"(a));
}

/* ------------------ 1. strided gather + RMSNorm(256) ------------------ */
__global__ void k_rmsnorm(const float* __restrict__ x, const float* __restrict__ w,
                          int axis, int L)
{
    int tok = blockIdx.x*8 + (threadIdx.x >> 5);
    if (tok >= NTOK) return;
    int lane = threadIdx.x & 31;
    int seq = tok / L, t = tok - seq*L;
    const float* xp = x + xoff(axis, seq, t);
    float v[8]; float ss = 0.f;
#pragma unroll
    for (int i = 0; i < 8; i++) { v[i] = xp[lane + 32*i]; ss += v[i]*v[i]; }
#pragma unroll
    for (int o = 16; o; o >>= 1) ss += __shfl_xor_sync(0xffffffffu, ss, o);
    float r = rsqrtf(ss*(1.f/HID) + 1e-6f);
    float* op = g_xn + tok*HID;
#pragma unroll
    for (int i = 0; i < 8; i++) op[lane + 32*i] = v[i]*r*w[lane + 32*i];
}

/* -------- weight transpose: W[K][N] -> WT[N][K] (run once/launch) ------ */
__global__ void k_transpose(const float* __restrict__ W, float* __restrict__ WT,
                            int K, int N)
{
    __shared__ float t[32][33];
    int n0 = blockIdx.x*32, k0 = blockIdx.y*32;
    int x = threadIdx.x, y = threadIdx.y;
#pragma unroll
    for (int i = 0; i < 32; i += 8) {
        int k = k0 + y + i, n = n0 + x;
        t[y+i][x] = (k < K && n < N) ? W[k*N + n] : 0.f;
    }
    __syncthreads();
#pragma unroll
    for (int i = 0; i < 32; i += 8) {
        int n = n0 + y + i, k = k0 + x;
        if (n < N && k < K) WT[n*K + k] = t[x][y+i];
    }
}

/* - 2/8. bf16-split HMMA GEMM: D[128,128] = A[128,K]*Wt[N,K]^T (~fp32) --
 * x = hi(bf16) + lo(bf16 of residual); D = Ah*Bh + Ah*Bl + Al*Bh via
 * mma.sync m16n8k16. B stored [n][k] == col-major operand -> non-trans
 * ldmatrix gives the correct fragment (lane/4 = n, half-pair along k).
 * Block 128x128, 8 warps (4m x 2n), warp tile 32x64, K-chunks of 32.
 * mode 0: write g_Z[row*PROJ+col]; mode 1: residual add into xout.      */
#define RS  80                     /* smem row stride bytes (40 halves)   */
#define AHI 0
#define ALO (128*RS)
#define BHI (2*128*RS)
#define BLO (3*128*RS)
#define GSM (128*132*4)            /* epilogue staging dominates (67584)  */
__global__ void __launch_bounds__(256)
k_mma(int asel, const float* __restrict__ Wt, int N, int K,
      int mode, float* xout, int axis, int L)
{
    extern __shared__ char sm[];
    uint32_t sb = smem_u32(sm);
    const float* A = asel ? g_y : g_xn;
    int m0 = blockIdx.y*128, n0 = blockIdx.x*128;
    int tid = threadIdx.x, lane = tid & 31, wid = tid >> 5;
    int wm = (wid & 3)*32, wn = (wid >> 2)*64;
    int row0 = tid >> 3, c4 = (tid & 7)*4;

    /* per-lane ldmatrix base offsets (x4: lanes 0-7 -> m0, 8-15 -> m1, ...) */
    int q = lane >> 3, r8 = lane & 7;
    uint32_t aoff = (uint32_t)((wm + (q & 1)*8 + r8)*RS + (q >> 1)*16);
    uint32_t boff = (uint32_t)((wn + (q >> 1)*8 + r8)*RS + (q & 1)*16);

    float acc[2][8][4];
#pragma unroll
    for (int mi = 0; mi < 2; mi++)
#pragma unroll
        for (int ni = 0; ni < 8; ni++)
#pragma unroll
            for (int p = 0; p < 4; p++) acc[mi][ni][p] = 0.f;

    int nch = K >> 5;
    float4 pa[4], pb[4];
#pragma unroll
    for (int i = 0; i < 4; i++)
        pa[i] = *(const float4*)&A[(size_t)(m0 + row0 + 32*i)*K + c4];
#pragma unroll
    for (int i = 0; i < 4; i++)
        pb[i] = (n0 + row0 + 32*i < N)
              ? *(const float4*)&Wt[(size_t)(n0 + row0 + 32*i)*K + c4]
              : make_float4(0.f,0.f,0.f,0.f);

    for (int c = 0; c < nch; c++) {
#pragma unroll
        for (int i = 0; i < 4; i++) {
            int r = row0 + 32*i;
            float4 v = pa[i];
            float h0 = __bfloat162float(__float2bfloat16(v.x));
            float h1 = __bfloat162float(__float2bfloat16(v.y));
            float h2 = __bfloat162float(__float2bfloat16(v.z));
            float h3 = __bfloat162float(__float2bfloat16(v.w));
            uint2 uh = make_uint2(bfpk(v.x, v.y), bfpk(v.z, v.w));
            uint2 ul = make_uint2(bfpk(v.x - h0, v.y - h1), bfpk(v.z - h2, v.w - h3));
            *(uint2*)(sm + AHI + r*RS + c4*2) = uh;
            *(uint2*)(sm + ALO + r*RS + c4*2) = ul;
            v = pb[i];
            h0 = __bfloat162float(__float2bfloat16(v.x));
            h1 = __bfloat162float(__float2bfloat16(v.y));
            h2 = __bfloat162float(__float2bfloat16(v.z));
            h3 = __bfloat162float(__float2bfloat16(v.w));
            uh = make_uint2(bfpk(v.x, v.y), bfpk(v.z, v.w));
            ul = make_uint2(bfpk(v.x - h0, v.y - h1), bfpk(v.z - h2, v.w - h3));
            *(uint2*)(sm + BHI + r*RS + c4*2) = uh;
            *(uint2*)(sm + BLO + r*RS + c4*2) = ul;
        }
        __syncthreads();
        if (c + 1 < nch) {
            int kt = (c+1)*32;
#pragma unroll
            for (int i = 0; i < 4; i++)
                pa[i] = *(const float4*)&A[(size_t)(m0 + row0 + 32*i)*K + kt + c4];
#pragma unroll
            for (int i = 0; i < 4; i++)
                pb[i] = (n0 + row0 + 32*i < N)
                      ? *(const float4*)&Wt[(size_t)(n0 + row0 + 32*i)*K + kt + c4]
                      : make_float4(0.f,0.f,0.f,0.f);
        }
#pragma unroll
        for (int kb = 0; kb < 2; kb++) {
            uint32_t ah[2][4], al[2][4];
            ldm4(ah[0], sb + AHI + aoff + kb*32);
            ldm4(ah[1], sb + AHI + aoff + 16*RS + kb*32);
            ldm4(al[0], sb + ALO + aoff + kb*32);
            ldm4(al[1], sb + ALO + aoff + 16*RS + kb*32);
#pragma unroll
            for (int np = 0; np < 4; np++) {
                uint32_t bh[4], bl[4];
                ldm4(bh, sb + BHI + boff + np*16*RS + kb*32);
                ldm4(bl, sb + BLO + boff + np*16*RS + kb*32);
#pragma unroll
                for (int mi = 0; mi < 2; mi++) {
                    mma16(acc[mi][np*2+0], ah[mi], bh[0], bh[1]);
                    mma16(acc[mi][np*2+0], ah[mi], bl[0], bl[1]);
                    mma16(acc[mi][np*2+0], al[mi], bh[0], bh[1]);
                    mma16(acc[mi][np*2+1], ah[mi], bh[2], bh[3]);
                    mma16(acc[mi][np*2+1], ah[mi], bl[2], bl[3]);
                    mma16(acc[mi][np*2+1], al[mi], bh[2], bh[3]);
                }
            }
        }
        __syncthreads();
    }

    /* epilogue: stage through smem for coalesced global access */
    float (*S)[132] = (float(*)[132])sm;
#pragma unroll
    for (int mi = 0; mi < 2; mi++)
#pragma unroll
        for (int ni = 0; ni < 8; ni++) {
            int r   = wm + mi*16 + (lane >> 2);
            int col = wn + ni*8 + (lane & 3)*2;
            S[r    ][col] = acc[mi][ni][0]; S[r    ][col+1] = acc[mi][ni][1];
            S[r + 8][col] = acc[mi][ni][2]; S[r + 8][col+1] = acc[mi][ni][3];
        }
    __syncthreads();
    int rr = tid >> 1, cb = (tid & 1)*64;
    if (mode == 0) {
        float* zp = g_Z + (size_t)(m0 + rr)*PROJ + n0 + cb;
#pragma unroll
        for (int j = 0; j < 16; j++) {
            if (n0 + cb + j*4 < N)
                *(float4*)&zp[j*4] = *(const float4*)&S[rr][cb + j*4];
        }
    } else {
        int row = m0 + rr;
        int seq = row / L, t = row - seq*L;
        float* op = xout + xoff(axis, seq, t) + n0 + cb;
#pragma unroll
        for (int j = 0; j < 16; j++) {
            float4 o = *(const float4*)&op[j*4];
            const float4 v = *(const float4*)&S[rr][cb + j*4];
            o.x += v.x; o.y += v.y; o.z += v.z; o.w += v.w;
            *(float4*)&op[j*4] = o;
        }
    }
}

/* ------- 3. causal conv(K=4)+SiLU over 640 ch, plus softplus(dt) ------- */
__global__ void k_convdt(const float* __restrict__ Wc, const float* __restrict__ bc,
                         const float* __restrict__ dtb, int L)
{
    int idx = blockIdx.x*256 + threadIdx.x;
    if (idx >= NTOK*(CONVDIM + NHEADS)) return;
    int tok = idx / (CONVDIM + NHEADS);
    int c   = idx - tok*(CONVDIM + NHEADS);
    int seq = tok / L, t = tok - seq*L;
    if (c < CONVDIM) {
        float acc = bc[c];
#pragma unroll
        for (int k = 0; k < 4; k++) {
            int tt = t - 3 + k;
            if (tt >= 0) acc += Wc[c*4 + k] * g_Z[(size_t)(seq*L + tt)*PROJ + DIN + c];
        }
        g_xBC[(size_t)tok*CONVDIM + c] = acc / (1.f + __expf(-acc));
    } else {
        int h = c - CONVDIM;
        float v = g_Z[(size_t)tok*PROJ + DIN + CONVDIM + h] + dtb[h];
        g_dt[tok*NHEADS + h] = (v > 20.f) ? v : log1pf(__expf(v));
    }
}

/* --------- 5. CB stored transposed: g_CB[seq][s][l] = B[s].C[l] -------- */
__global__ void k_cb(int L)
{
    __shared__ __align__(16) float Bt[64][68], Ct[64][68];
    int seq = blockIdx.x;
    int s0 = blockIdx.y*64, l0 = blockIdx.z*64;
    int tid = threadIdx.x;
    int n = tid & 63, r = tid >> 6;
#pragma unroll 4
    for (int i = 0; i < 16; i++) {
        int row = r + 4*i;
        int gs = s0 + row, gl = l0 + row;
        Bt[n][row] = (gs < L) ? g_xBC[(size_t)(seq*L + gs)*CONVDIM + DIN + n]          : 0.f;
        Ct[n][row] = (gl < L) ? g_xBC[(size_t)(seq*L + gl)*CONVDIM + DIN + DSTATE + n] : 0.f;
    }
    __syncthreads();
    int tx = tid & 15, ty = tid >> 4;
    float acc[4][4] = {};
#pragma unroll 8
    for (int k = 0; k < 64; k++) {
        float4 a = *(const float4*)&Bt[k][ty*4];
        float4 b = *(const float4*)&Ct[k][tx*4];
        acc[0][0]+=a.x*b.x; acc[0][1]+=a.x*b.y; acc[0][2]+=a.x*b.z; acc[0][3]+=a.x*b.w;
        acc[1][0]+=a.y*b.x; acc[1][1]+=a.y*b.y; acc[1][2]+=a.y*b.z; acc[1][3]+=a.y*b.w;
        acc[2][0]+=a.z*b.x; acc[2][1]+=a.z*b.y; acc[2][2]+=a.z*b.z; acc[2][3]+=a.z*b.w;
        acc[3][0]+=a.w*b.x; acc[3][1]+=a.w*b.y; acc[3][2]+=a.w*b.z; acc[3][3]+=a.w*b.w;
    }
#pragma unroll
    for (int i = 0; i < 4; i++) {
        int gs = s0 + ty*4 + i;
#pragma unroll
        for (int j = 0; j < 4; j++) {
            int gl = l0 + tx*4 + j;
            if (gs < L && gl < L) g_CB[(size_t)(seq*L + gs)*L + gl] = acc[i][j];
        }
    }
}

/* --- 6. SSD with in-block cumsum (fwd+bwd combined, diagonal x2) ------- */
__global__ void k_ssd(const float* __restrict__ Alog, int L)
{
    __shared__ float cum[192], dts[192];
    __shared__ __align__(16) float Wt[64][68];
    __shared__ __align__(16) float Xs[64][68];
    int seq = blockIdx.x, h = blockIdx.y, l0 = blockIdx.z*64;
    int tid = threadIdx.x;
    float A = -expf(Alog[h]);

    for (int t = tid; t < L; t += 256) {
        float d = g_dt[(seq*L + t)*NHEADS + h];
        dts[t] = d;
        cum[t] = d*A;
    }
    __syncthreads();
    for (int off = 1; off < L; off <<= 1) {
        float v = 0.f;
        if (tid < L && tid >= off) v = cum[tid - off];
        __syncthreads();
        if (tid < L) cum[tid] += v;
        __syncthreads();
    }

    int tx = tid & 15, ty = tid >> 4;
    int fc = tid & 63, fr = tid >> 6;
    float acc[4][4] = {};

    for (int s0 = 0; s0 < L; s0 += 64) {
#pragma unroll 4
        for (int i = 0; i < 16; i++) {
            int s = fr + 4*i;
            int gs = s0 + s;
            Xs[s][fc] = (gs < L) ? g_xBC[(size_t)(seq*L + gs)*CONVDIM + h*HEADP + fc] : 0.f;
        }
#pragma unroll 4
        for (int i = 0; i < 16; i++) {
            int sW = fr + 4*i, lW = fc;
            int gs = s0 + sW, gl = l0 + lW;
            float w = 0.f;
            if (gl < L && gs < L) {
                float cb = g_CB[(size_t)(seq*L + gs)*L + gl];
                float e;
                if (gs < gl)       e = __expf(cum[gl] - cum[gs]);
                else if (gs == gl) e = 2.f;
                else               e = __expf((cum[gs] - dts[gs]*A) - (cum[gl] - dts[gl]*A));
                w = cb * e * dts[gs];
            }
            Wt[sW][lW] = w;
        }
        __syncthreads();
#pragma unroll 8
        for (int k = 0; k < 64; k++) {
            float4 a = *(const float4*)&Wt[k][ty*4];
            float4 b = *(const float4*)&Xs[k][tx*4];
            acc[0][0]+=a.x*b.x; acc[0][1]+=a.x*b.y; acc[0][2]+=a.x*b.z; acc[0][3]+=a.x*b.w;
            acc[1][0]+=a.y*b.x; acc[1][1]+=a.y*b.y; acc[1][2]+=a.y*b.z; acc[1][3]+=a.y*b.w;
            acc[2][0]+=a.z*b.x; acc[2][1]+=a.z*b.y; acc[2][2]+=a.z*b.z; acc[2][3]+=a.z*b.w;
            acc[3][0]+=a.w*b.x; acc[3][1]+=a.w*b.y; acc[3][2]+=a.w*b.z; acc[3][3]+=a.w*b.w;
        }
        __syncthreads();
    }
#pragma unroll
    for (int i = 0; i < 4; i++) {
        int gl = l0 + ty*4 + i;
        if (gl < L) {
            float* yp = g_y + (size_t)(seq*L + gl)*DIN + h*HEADP;
#pragma unroll
            for (int j = 0; j < 4; j++) yp[tx*4 + j] = acc[i][j];
        }
    }
}

/* ---------- 7. (y + D*xh) * silu(z), then RMSNorm(512) * gn_w ---------- */
__global__ void k_gate(const float* __restrict__ Dv, const float* __restrict__ gnw)
{
    __shared__ float red[8];
    int tok = blockIdx.x, tid = threadIdx.x;
    float v[2]; float ss = 0.f;
#pragma unroll
    for (int i = 0; i < 2; i++) {
        int d = tid + 256*i;
        float y = g_y[(size_t)tok*DIN + d] + Dv[d >> 6]*g_xBC[(size_t)tok*CONVDIM + d];
        float z = g_Z[(size_t)tok*PROJ + d];
        y *= z / (1.f + __expf(-z));
        v[i] = y; ss += y*y;
    }
#pragma unroll
    for (int o = 16; o; o >>= 1) ss += __shfl_xor_sync(0xffffffffu, ss, o);
    if ((tid & 31) == 0) red[tid >> 5] = ss;
    __syncthreads();
    if (tid < 32) {
        float s = (tid < 8) ? red[tid] : 0.f;
#pragma unroll
        for (int o = 4; o; o >>= 1) s += __shfl_xor_sync(0xffffffffu, s, o);
        if (tid == 0) red[0] = s;
    }
    __syncthreads();
    float r = rsqrtf(red[0]*(1.f/DIN) + 1e-6f);
#pragma unroll
    for (int i = 0; i < 2; i++) {
        int d = tid + 256*i;
        g_y[(size_t)tok*DIN + d] = v[i]*r*gnw[d];
    }
}

/* ----------------------------- host side ------------------------------ */
static void run_call(float* out, const float* const* P,
                     const float* WinT, const float* WoutT, int li, int axis)
{
    const float* nw   = P[0] + li*HID;
    const float* Wc   = P[2] + li*CONVDIM*4;
    const float* bc   = P[3] + li*CONVDIM;
    const float* dtb  = P[4] + li*NHEADS;
    const float* Alog = P[5] + li*NHEADS;
    const float* Dv   = P[6] + li*NHEADS;
    const float* gnw  = P[7] + li*DIN;
    int L = (axis == 0) ? Tn : NBn;
    int nseq = NTOK / L;
    int lt = (L + 63)/64;

    k_rmsnorm<<<NTOK/8, 256>>>(out, nw, axis, L);
    k_mma<<<dim3((PROJ + 127)/128, NTOK/128), 256, GSM>>>(0, WinT, PROJ, HID, 0, nullptr, axis, L);
    k_convdt<<<(NTOK*(CONVDIM + NHEADS) + 255)/256, 256>>>(Wc, bc, dtb, L);
    k_cb<<<dim3(nseq, lt, lt), 256>>>(L);
    k_ssd<<<dim3(nseq, NHEADS, lt), 256>>>(Alog, L);
    k_gate<<<NTOK, 256>>>(Dv, gnw);
    k_mma<<<dim3(HID/128, NTOK/128), 256, GSM>>>(1, WoutT, HID, DIN, 1, out, axis, L);
}

extern "C" void kernel_launch(void* const* d_in, const int* in_sizes, int n_in,
                              void* d_out, int out_size)
{
    static int smem_set = 0;
    if (!smem_set) {
        cudaFuncSetAttribute(k_mma, cudaFuncAttributeMaxDynamicSharedMemorySize, GSM);
        smem_set = 1;
    }

    float* out = (float*)d_out;
    cudaMemcpyAsync(out, d_in[0], (size_t)out_size*sizeof(float),
                    cudaMemcpyDeviceToDevice);
    const float* tp[9]; const float* bp[9];
    for (int i = 0; i < 9; i++) {
        tp[i] = (const float*)d_in[1 + i];
        bp[i] = (const float*)d_in[10 + i];
    }

    float *winT, *woutT;
    cudaGetSymbolAddress((void**)&winT,  g_WinT);
    cudaGetSymbolAddress((void**)&woutT, g_WoutT);

    for (int ax = 0; ax < 2; ax++) {
        const float* const* P = ax ? bp : tp;
        for (int li = 0; li < 2; li++) {
            int idx = ax*2 + li;
            k_transpose<<<dim3((PROJ+31)/32, (HID+31)/32), dim3(32,8)>>>(
                P[1] + li*HID*PROJ, winT + (size_t)idx*PROJ*HID, HID, PROJ);
            k_transpose<<<dim3((HID+31)/32, (DIN+31)/32), dim3(32,8)>>>(
                P[8] + li*DIN*HID, woutT + (size_t)idx*HID*DIN, DIN, HID);
        }
    }

    for (int li = 0; li < 2; li++) {
        run_call(out, tp, winT + (size_t)(0*2+li)*PROJ*HID,
                          woutT + (size_t)(0*2+li)*HID*DIN, li, 0);
        run_call(out, bp, winT + (size_t)(1*2+li)*PROJ*HID,
                          woutT + (size_t)(1*2+li)*HID*DIN, li, 1);
    }
}